// round 5
// baseline (speedup 1.0000x reference)
#include <cuda_runtime.h>
#include <cuda_bf16.h>
#include <math.h>
#include <cstdint>

#define BB 512
#define HH 2048
#define EE 2048
#define TT 256
#define NG 8192    // 4*H, permuted: n' = hc*4 + gate (i,f,g,o)

// ------------------------------------------------------------------ state
__device__ __align__(128) __nv_bfloat16 g_h_hi[2][BB * HH];
__device__ __align__(128) __nv_bfloat16 g_h_lo[2][BB * HH];
__device__ __align__(128) float         g_c[BB * HH];
__device__ __align__(128) __nv_bfloat16 g_w_hi[NG * HH];
__device__ __align__(128) __nv_bfloat16 g_w_lo[NG * HH];
__device__ __align__(128) float         g_bsum[NG];
__device__ __align__(128) float         g_wih0[NG];
__device__ __align__(128) float         g_wih1[NG];

// ------------------------------------------------------------------ helpers
#define CP16(dst, src)  asm volatile("cp.async.cg.shared.global [%0], [%1], 16;" :: "r"(dst), "l"(src))
#define CP_COMMIT()     asm volatile("cp.async.commit_group;" ::: "memory")
#define CP_WAIT1()      asm volatile("cp.async.wait_group 1;" ::: "memory")
#define CP_WAIT0()      asm volatile("cp.async.wait_group 0;" ::: "memory")

#define LDSM4(r, a) \
    asm volatile("ldmatrix.sync.aligned.m8n8.x4.shared.b16 {%0,%1,%2,%3}, [%4];" \
        : "=r"((r)[0]), "=r"((r)[1]), "=r"((r)[2]), "=r"((r)[3]) : "r"(a))

__device__ __forceinline__ uint32_t smem_u32(const void* p) {
    uint32_t a;
    asm("{ .reg .u64 t; cvta.to.shared.u64 t, %1; cvt.u32.u64 %0, t; }" : "=r"(a) : "l"(p));
    return a;
}

__device__ __forceinline__ void mma16816(float* d, const uint32_t* a, const uint32_t* b) {
    asm volatile(
        "mma.sync.aligned.m16n8k16.row.col.f32.bf16.bf16.f32 "
        "{%0,%1,%2,%3}, {%4,%5,%6,%7}, {%8,%9}, {%0,%1,%2,%3};"
        : "+f"(d[0]), "+f"(d[1]), "+f"(d[2]), "+f"(d[3])
        : "r"(a[0]), "r"(a[1]), "r"(a[2]), "r"(a[3]), "r"(b[0]), "r"(b[1]));
}

__device__ __forceinline__ float fsigm(float x) { return 1.0f / (1.0f + __expf(-x)); }
__device__ __forceinline__ float ftanh(float x) {
    if (x > 8.0f) return 1.0f;
    if (x < -8.0f) return -1.0f;
    float e = __expf(2.0f * x);
    return (e - 1.0f) / (e + 1.0f);
}

// ------------------------------------------------------------------ prep
__global__ void prep_w_kernel(const float* __restrict__ W_hh) {
    int np = blockIdx.x;                 // 0..NG-1
    int g = np & 3, hc = np >> 2;
    const float* src = W_hh + (size_t)(g * HH + hc) * HH;
    __nv_bfloat16* dh = g_w_hi + (size_t)np * HH;
    __nv_bfloat16* dl = g_w_lo + (size_t)np * HH;
#pragma unroll
    for (int j = 0; j < HH / 256; j++) {
        int k = threadIdx.x + j * 256;
        float w = src[k];
        __nv_bfloat16 hi = __float2bfloat16_rn(w);
        dh[k] = hi;
        dl[k] = __float2bfloat16_rn(w - __bfloat162float(hi));
    }
}

__global__ void prep_misc_kernel(const float* __restrict__ b_ih, const float* __restrict__ b_hh,
                                 const float* __restrict__ W_ih) {
    int np = blockIdx.x * 256 + threadIdx.x;
    int g = np & 3, hc = np >> 2;
    int j = g * HH + hc;
    g_bsum[np] = b_ih[j] + b_hh[j];
    g_wih0[np] = W_ih[2 * j + 0];
    g_wih1[np] = W_ih[2 * j + 1];
}

// ------------------------------------------------------------------ h0 (fp32 SIMT, one-time)
#define KC 16
__global__ __launch_bounds__(256, 2)
void h0_kernel(const float* __restrict__ emb, const float* __restrict__ W,
               const float* __restrict__ bias) {
    __shared__ float As[KC][64];
    __shared__ float Bs[KC][64];
    int tid = threadIdx.x;
    int m0 = blockIdx.y * 64, n0 = blockIdx.x * 64;
    int lrow = tid >> 2, lk4 = (tid & 3) * 4;
    int tx_m = tid >> 4, tx_n = tid & 15;

    float acc[4][4];
#pragma unroll
    for (int i = 0; i < 4; i++)
#pragma unroll
        for (int j = 0; j < 4; j++) acc[i][j] = 0.0f;

    for (int k0 = 0; k0 < EE; k0 += KC) {
        float4 av = *(const float4*)&emb[(m0 + lrow) * EE + k0 + lk4];
        float4 bv = *(const float4*)&W[(n0 + lrow) * EE + k0 + lk4];
        __syncthreads();
        As[lk4 + 0][lrow] = av.x; As[lk4 + 1][lrow] = av.y;
        As[lk4 + 2][lrow] = av.z; As[lk4 + 3][lrow] = av.w;
        Bs[lk4 + 0][lrow] = bv.x; Bs[lk4 + 1][lrow] = bv.y;
        Bs[lk4 + 2][lrow] = bv.z; Bs[lk4 + 3][lrow] = bv.w;
        __syncthreads();
#pragma unroll
        for (int kk = 0; kk < KC; kk++) {
            float a[4], b[4];
            *(float4*)a = *(float4*)&As[kk][tx_m * 4];
            *(float4*)b = *(float4*)&Bs[kk][tx_n * 4];
#pragma unroll
            for (int mi = 0; mi < 4; mi++)
#pragma unroll
                for (int ni = 0; ni < 4; ni++) acc[mi][ni] += a[mi] * b[ni];
        }
    }
#pragma unroll
    for (int mi = 0; mi < 4; mi++) {
        int m = m0 + tx_m * 4 + mi;
#pragma unroll
        for (int ni = 0; ni < 4; ni++) {
            int n = n0 + tx_n * 4 + ni;
            float h = acc[mi][ni] + bias[n];
            __nv_bfloat16 hi = __float2bfloat16_rn(h);
            g_h_hi[0][m * HH + n] = hi;
            g_h_lo[0][m * HH + n] = __float2bfloat16_rn(h - __bfloat162float(hi));
        }
    }
}

// ------------------------------------------------------------------ main LSTM step (mma.sync bf16 3-pass, ldmatrix)
// CTA tile: 128 M x 128 N, 256 threads = 8 warps (4 m x 2 n of 32x64).
// Grid (64, 4) = 256 CTAs, 2 CTAs/SM.
#define BKC 32           // K per chunk
#define ROWB 80          // padded row bytes (32 bf16 = 64B data + 16B pad)
#define NCHUNK 64        // 2048 / 32
#define A_HI_OFF 0
#define A_LO_OFF 10240   // 128*80
#define B_HI_OFF 20480
#define B_LO_OFF 30720
#define STAGE_BYTES 40960
#define XS_OFF 0
#define STAGE0 1024
#define SMEM_TOTAL (STAGE0 + 2 * STAGE_BYTES)

__device__ __forceinline__ void load_chunk(char* smem, int stage_idx, int k0, int m0, int n0,
                                           const __nv_bfloat16* hh, const __nv_bfloat16* hl,
                                           int tid) {
    uint32_t st = smem_u32(smem + STAGE0 + stage_idx * STAGE_BYTES);
#pragma unroll
    for (int p = 0; p < 2; p++) {   // A: 128 rows x 4 chunks of 16B
        int u = tid + p * 256;
        int row = u >> 2, c16 = u & 3;
        uint32_t d = st + row * ROWB + c16 * 16;
        size_t goff = (size_t)(m0 + row) * HH + k0 + c16 * 8;
        CP16(d + A_HI_OFF, hh + goff);
        CP16(d + A_LO_OFF, hl + goff);
    }
#pragma unroll
    for (int p = 0; p < 2; p++) {   // B: 128 rows x 4 chunks of 16B
        int u = tid + p * 256;
        int row = u >> 2, c16 = u & 3;
        uint32_t d = st + row * ROWB + c16 * 16;
        size_t goff = (size_t)(n0 + row) * HH + k0 + c16 * 8;
        CP16(d + B_HI_OFF, g_w_hi + goff);
        CP16(d + B_LO_OFF, g_w_lo + goff);
    }
}

__global__ __launch_bounds__(256, 2)
void lstm_step_mma(const float* __restrict__ out, int t) {
    extern __shared__ char smem[];
    float* x_s = (float*)(smem + XS_OFF);       // [128][2]
    int tid = threadIdx.x;
    int wid = tid >> 5, lane = tid & 31;
    int g = lane >> 2, tig = lane & 3;
    int wm = wid & 3, wn = wid >> 2;            // 4 m-warps x 2 n-warps
    int n0 = blockIdx.x * 128, m0 = blockIdx.y * 128;
    int src = t & 1, dst = src ^ 1;
    const __nv_bfloat16* hh = g_h_hi[src];
    const __nv_bfloat16* hl = g_h_lo[src];
    uint32_t sbase = smem_u32(smem + STAGE0);

    // ldmatrix per-lane row offsets (within stage)
    uint32_t aoff[2];
#pragma unroll
    for (int mi = 0; mi < 2; mi++)
        aoff[mi] = (uint32_t)((wm * 32 + mi * 16 + (lane & 15)) * ROWB + ((lane >> 4) * 16));
    uint32_t boff[4];
#pragma unroll
    for (int nip = 0; nip < 4; nip++)
        boff[nip] = (uint32_t)((wn * 64 + nip * 16 + ((lane >> 4) << 3) + (lane & 7)) * ROWB
                               + (((lane >> 3) & 1) * 16));

    // prev coords -> smem
    if (tid < 128) {
        float x0 = 0.0f, x1 = 0.0f;
        if (t > 0) {
            x0 = out[((m0 + tid) * TT + t - 1) * 2 + 0];
            x1 = out[((m0 + tid) * TT + t - 1) * 2 + 1];
        }
        x_s[tid * 2 + 0] = x0;
        x_s[tid * 2 + 1] = x1;
    }

    float acc[2][8][4];
#pragma unroll
    for (int mi = 0; mi < 2; mi++)
#pragma unroll
        for (int ni = 0; ni < 8; ni++)
#pragma unroll
            for (int j = 0; j < 4; j++) acc[mi][ni][j] = 0.0f;

    load_chunk(smem, 0, 0, m0, n0, hh, hl, tid);
    CP_COMMIT();

    for (int c = 0; c < NCHUNK; c++) {
        if (c > 0) __syncthreads();     // all warps done computing chunk c-1 -> stage (c+1)&1 reusable
        if (c + 1 < NCHUNK) {
            load_chunk(smem, (c + 1) & 1, (c + 1) * BKC, m0, n0, hh, hl, tid);
            CP_COMMIT();
            CP_WAIT1();                 // chunk c data arrived
        } else {
            CP_WAIT0();
        }
        __syncthreads();                // publish chunk c to all warps

        uint32_t stage = sbase + (c & 1) * STAGE_BYTES;
#pragma unroll
        for (int kk = 0; kk < 2; kk++) {
            uint32_t kb = kk * 32;
            uint32_t ah[2][4], al[2][4];
#pragma unroll
            for (int mi = 0; mi < 2; mi++) {
                LDSM4(ah[mi], stage + A_HI_OFF + aoff[mi] + kb);
                LDSM4(al[mi], stage + A_LO_OFF + aoff[mi] + kb);
            }
#pragma unroll
            for (int nip = 0; nip < 4; nip++) {
                uint32_t bh[4], bl[4];
                LDSM4(bh, stage + B_HI_OFF + boff[nip] + kb);
                LDSM4(bl, stage + B_LO_OFF + boff[nip] + kb);
#pragma unroll
                for (int ni2 = 0; ni2 < 2; ni2++)
#pragma unroll
                    for (int mi = 0; mi < 2; mi++)
                        mma16816(acc[mi][nip * 2 + ni2], ah[mi], bh + ni2 * 2);
#pragma unroll
                for (int ni2 = 0; ni2 < 2; ni2++)
#pragma unroll
                    for (int mi = 0; mi < 2; mi++)
                        mma16816(acc[mi][nip * 2 + ni2], ah[mi], bl + ni2 * 2);
#pragma unroll
                for (int ni2 = 0; ni2 < 2; ni2++)
#pragma unroll
                    for (int mi = 0; mi < 2; mi++)
                        mma16816(acc[mi][nip * 2 + ni2], al[mi], bh + ni2 * 2);
            }
        }
    }

    // ------------------------------ fused LSTM epilogue
#pragma unroll
    for (int mi = 0; mi < 2; mi++) {
        int r0 = wm * 32 + mi * 16 + g;
#pragma unroll
        for (int ni = 0; ni < 8; ni++) {
            float o0 = acc[mi][ni][0], o1 = acc[mi][ni][1];
            float o2 = acc[mi][ni][2], o3 = acc[mi][ni][3];
            float p0 = __shfl_xor_sync(0xFFFFFFFFu, o0, 1);
            float p1 = __shfl_xor_sync(0xFFFFFFFFu, o1, 1);
            float p2 = __shfl_xor_sync(0xFFFFFFFFu, o2, 1);
            float p3 = __shfl_xor_sync(0xFFFFFFFFu, o3, 1);
            if ((tig & 1) == 0) {
                int col = wn * 64 + ni * 8 + 2 * tig;
                int np = n0 + col;
                float4 bs = *(const float4*)&g_bsum[np];
                float4 wa = *(const float4*)&g_wih0[np];
                float4 wb = *(const float4*)&g_wih1[np];
                int hc = np >> 2;
#pragma unroll
                for (int rr = 0; rr < 2; rr++) {
                    int rl = r0 + rr * 8;
                    int m = m0 + rl;
                    float x0 = x_s[rl * 2 + 0], x1 = x_s[rl * 2 + 1];
                    float vi = rr ? o2 : o0, vf = rr ? o3 : o1;
                    float vg = rr ? p2 : p0, vo = rr ? p3 : p1;
                    float pi = vi + bs.x + x0 * wa.x + x1 * wb.x;
                    float pf = vf + bs.y + x0 * wa.y + x1 * wb.y;
                    float pg = vg + bs.z + x0 * wa.z + x1 * wb.z;
                    float po = vo + bs.w + x0 * wa.w + x1 * wb.w;
                    float cp = (t == 0) ? 0.0f : g_c[m * HH + hc];
                    float cn = fsigm(pf) * cp + fsigm(pi) * ftanh(pg);
                    g_c[m * HH + hc] = cn;
                    float h = fsigm(po) * ftanh(cn);
                    __nv_bfloat16 hi = __float2bfloat16_rn(h);
                    g_h_hi[dst][m * HH + hc] = hi;
                    g_h_lo[dst][m * HH + hc] = __float2bfloat16_rn(h - __bfloat162float(hi));
                }
            }
        }
    }
}

// ------------------------------------------------------------------ head (vectorized)
__global__ void head_kernel(const float* __restrict__ W_out, const float* __restrict__ b_out,
                            const float* __restrict__ W_stop, const float* __restrict__ b_stop,
                            float* __restrict__ out, int t) {
    int wid = threadIdx.x >> 5, lane = threadIdx.x & 31;
    int b = blockIdx.x * 8 + wid;
    const uint4* hh4 = (const uint4*)(g_h_hi[(t & 1) ^ 1] + b * HH);
    const uint4* hl4 = (const uint4*)(g_h_lo[(t & 1) ^ 1] + b * HH);

    float s0 = 0.0f, s1 = 0.0f, ss = 0.0f;
#pragma unroll
    for (int it = 0; it < 8; it++) {
        int v = it * 32 + lane;
        uint4 vh = hh4[v], vl = hl4[v];
        int e = v * 8;
#pragma unroll
        for (int w = 0; w < 4; w++) {
            uint32_t uh = (&vh.x)[w], ul = (&vl.x)[w];
            float2 fh = __bfloat1622float2(*(__nv_bfloat162*)&uh);
            float2 fl = __bfloat1622float2(*(__nv_bfloat162*)&ul);
            float h0 = fh.x + fl.x, h1 = fh.y + fl.y;
            int i = e + w * 2;
            float2 w0 = *(const float2*)&W_out[i];
            float2 w1 = *(const float2*)&W_out[HH + i];
            float2 wsv = *(const float2*)&W_stop[i];
            s0 += h0 * w0.x + h1 * w0.y;
            s1 += h0 * w1.x + h1 * w1.y;
            ss += h0 * wsv.x + h1 * wsv.y;
        }
    }
#pragma unroll
    for (int o = 16; o > 0; o >>= 1) {
        s0 += __shfl_down_sync(0xFFFFFFFFu, s0, o);
        s1 += __shfl_down_sync(0xFFFFFFFFu, s1, o);
        ss += __shfl_down_sync(0xFFFFFFFFu, ss, o);
    }
    if (lane == 0) {
        out[(b * TT + t) * 2 + 0] = s0 + b_out[0];
        out[(b * TT + t) * 2 + 1] = s1 + b_out[1];
        out[BB * TT * 2 + b * TT + t] = fsigm(ss + b_stop[0]);
    }
}

// ------------------------------------------------------------------ launch
extern "C" void kernel_launch(void* const* d_in, const int* in_sizes, int n_in,
                              void* d_out, int out_size) {
    const float* emb     = (const float*)d_in[0];
    const float* W_embed = (const float*)d_in[2];
    const float* b_embed = (const float*)d_in[3];
    const float* W_ih    = (const float*)d_in[4];
    const float* b_ih    = (const float*)d_in[5];
    const float* W_hh    = (const float*)d_in[6];
    const float* b_hh    = (const float*)d_in[7];
    const float* W_out   = (const float*)d_in[8];
    const float* b_out   = (const float*)d_in[9];
    const float* W_stop  = (const float*)d_in[10];
    const float* b_stop  = (const float*)d_in[11];
    float* out = (float*)d_out;

    cudaFuncSetAttribute(lstm_step_mma, cudaFuncAttributeMaxDynamicSharedMemorySize, SMEM_TOTAL);

    prep_w_kernel<<<NG, 256>>>(W_hh);
    prep_misc_kernel<<<NG / 256, 256>>>(b_ih, b_hh, W_ih);
    h0_kernel<<<dim3(HH / 64, BB / 64), 256>>>(emb, W_embed, b_embed);

    for (int t = 0; t < TT; t++) {
        lstm_step_mma<<<dim3(64, 4), 256, SMEM_TOTAL>>>(out, t);
        head_kernel<<<64, 256>>>(W_out, b_out, W_stop, b_stop, out, t);
    }
}

// round 6
// speedup vs baseline: 1.1345x; 1.1345x over previous
#include <cuda_runtime.h>
#include <cuda_bf16.h>
#include <math.h>
#include <cstdint>

#define BB 512
#define HH 2048
#define EE 2048
#define TT 256
#define NG 8192    // 4*H, permuted: n' = hc*4 + gate (i,f,g,o)

// ------------------------------------------------------------------ state
__device__ __align__(128) __nv_bfloat16 g_h_hi[2][BB * HH];
__device__ __align__(128) __nv_bfloat16 g_h_lo[2][BB * HH];
__device__ __align__(128) float         g_c[BB * HH];
__device__ __align__(128) __nv_bfloat16 g_w_hi[NG * HH];
__device__ __align__(128) __nv_bfloat16 g_w_lo[NG * HH];
__device__ __align__(128) float         g_bsum[NG];
__device__ __align__(128) float         g_wih0[NG];
__device__ __align__(128) float         g_wih1[NG];

// ------------------------------------------------------------------ helpers
#define CP16(dst, src)  asm volatile("cp.async.cg.shared.global [%0], [%1], 16;" :: "r"(dst), "l"(src))
#define CP_COMMIT()     asm volatile("cp.async.commit_group;" ::: "memory")
#define CP_WAITG(n)     asm volatile("cp.async.wait_group %0;" :: "n"(n) : "memory")

#define LDSM4(r, a) \
    asm volatile("ldmatrix.sync.aligned.m8n8.x4.shared.b16 {%0,%1,%2,%3}, [%4];" \
        : "=r"((r)[0]), "=r"((r)[1]), "=r"((r)[2]), "=r"((r)[3]) : "r"(a))

__device__ __forceinline__ uint32_t smem_u32(const void* p) {
    uint32_t a;
    asm("{ .reg .u64 t; cvta.to.shared.u64 t, %1; cvt.u32.u64 %0, t; }" : "=r"(a) : "l"(p));
    return a;
}

__device__ __forceinline__ void mma16816(float* d, const uint32_t* a, const uint32_t* b) {
    asm volatile(
        "mma.sync.aligned.m16n8k16.row.col.f32.bf16.bf16.f32 "
        "{%0,%1,%2,%3}, {%4,%5,%6,%7}, {%8,%9}, {%0,%1,%2,%3};"
        : "+f"(d[0]), "+f"(d[1]), "+f"(d[2]), "+f"(d[3])
        : "r"(a[0]), "r"(a[1]), "r"(a[2]), "r"(a[3]), "r"(b[0]), "r"(b[1]));
}

__device__ __forceinline__ float fsigm(float x) { return 1.0f / (1.0f + __expf(-x)); }
__device__ __forceinline__ float ftanh(float x) {
    if (x > 8.0f) return 1.0f;
    if (x < -8.0f) return -1.0f;
    float e = __expf(2.0f * x);
    return (e - 1.0f) / (e + 1.0f);
}

// swizzled 64B-row tile: phys(row, c16) = row*64 + ((c16 ^ ((row>>1)&3))<<4)
__device__ __forceinline__ uint32_t tswz(int row, int c16) {
    return (uint32_t)(row * 64 + (((c16 ^ ((row >> 1) & 3)) & 3) << 4));
}

// ------------------------------------------------------------------ prep
__global__ void prep_w_kernel(const float* __restrict__ W_hh) {
    int np = blockIdx.x;                 // 0..NG-1
    int g = np & 3, hc = np >> 2;
    const float* src = W_hh + (size_t)(g * HH + hc) * HH;
    __nv_bfloat16* dh = g_w_hi + (size_t)np * HH;
    __nv_bfloat16* dl = g_w_lo + (size_t)np * HH;
#pragma unroll
    for (int j = 0; j < HH / 256; j++) {
        int k = threadIdx.x + j * 256;
        float w = src[k];
        __nv_bfloat16 hi = __float2bfloat16_rn(w);
        dh[k] = hi;
        dl[k] = __float2bfloat16_rn(w - __bfloat162float(hi));
    }
}

__global__ void prep_misc_kernel(const float* __restrict__ b_ih, const float* __restrict__ b_hh,
                                 const float* __restrict__ W_ih) {
    int np = blockIdx.x * 256 + threadIdx.x;
    int g = np & 3, hc = np >> 2;
    int j = g * HH + hc;
    g_bsum[np] = b_ih[j] + b_hh[j];
    g_wih0[np] = W_ih[2 * j + 0];
    g_wih1[np] = W_ih[2 * j + 1];
}

// ------------------------------------------------------------------ h0 (fp32 SIMT, one-time)
#define KC 16
__global__ __launch_bounds__(256, 2)
void h0_kernel(const float* __restrict__ emb, const float* __restrict__ W,
               const float* __restrict__ bias) {
    __shared__ float As[KC][64];
    __shared__ float Bs[KC][64];
    int tid = threadIdx.x;
    int m0 = blockIdx.y * 64, n0 = blockIdx.x * 64;
    int lrow = tid >> 2, lk4 = (tid & 3) * 4;
    int tx_m = tid >> 4, tx_n = tid & 15;

    float acc[4][4];
#pragma unroll
    for (int i = 0; i < 4; i++)
#pragma unroll
        for (int j = 0; j < 4; j++) acc[i][j] = 0.0f;

    for (int k0 = 0; k0 < EE; k0 += KC) {
        float4 av = *(const float4*)&emb[(m0 + lrow) * EE + k0 + lk4];
        float4 bv = *(const float4*)&W[(n0 + lrow) * EE + k0 + lk4];
        __syncthreads();
        As[lk4 + 0][lrow] = av.x; As[lk4 + 1][lrow] = av.y;
        As[lk4 + 2][lrow] = av.z; As[lk4 + 3][lrow] = av.w;
        Bs[lk4 + 0][lrow] = bv.x; Bs[lk4 + 1][lrow] = bv.y;
        Bs[lk4 + 2][lrow] = bv.z; Bs[lk4 + 3][lrow] = bv.w;
        __syncthreads();
#pragma unroll
        for (int kk = 0; kk < KC; kk++) {
            float a[4], b[4];
            *(float4*)a = *(float4*)&As[kk][tx_m * 4];
            *(float4*)b = *(float4*)&Bs[kk][tx_n * 4];
#pragma unroll
            for (int mi = 0; mi < 4; mi++)
#pragma unroll
                for (int ni = 0; ni < 4; ni++) acc[mi][ni] += a[mi] * b[ni];
        }
    }
#pragma unroll
    for (int mi = 0; mi < 4; mi++) {
        int m = m0 + tx_m * 4 + mi;
#pragma unroll
        for (int ni = 0; ni < 4; ni++) {
            int n = n0 + tx_n * 4 + ni;
            float h = acc[mi][ni] + bias[n];
            __nv_bfloat16 hi = __float2bfloat16_rn(h);
            g_h_hi[0][m * HH + n] = hi;
            g_h_lo[0][m * HH + n] = __float2bfloat16_rn(h - __bfloat162float(hi));
        }
    }
}

// ------------------------------------------------------------------ main LSTM step
// CTA tile: 128 M x 128 N, 256 threads = 8 warps (4 m x 2 n of 32x64).
// Grid (64, 4) = 256 CTAs, 2 CTAs/SM. 3-stage swizzled pipeline, 1 sync/chunk.
#define BKC 32           // K per chunk
#define NCHUNK 64        // 2048 / 32
#define TILE_BYTES 8192  // 128 rows x 64B
#define A_HI_OFF 0
#define A_LO_OFF 8192
#define B_HI_OFF 16384
#define B_LO_OFF 24576
#define STAGE_BYTES 32768
#define XS_OFF 0
#define STAGE0 1024
#define SMEM_TOTAL (STAGE0 + 3 * STAGE_BYTES)

__device__ __forceinline__ void load_chunk(uint32_t sbase, int stage_idx, int k0, int m0, int n0,
                                           const __nv_bfloat16* hh, const __nv_bfloat16* hl,
                                           int tid) {
    uint32_t st = sbase + stage_idx * STAGE_BYTES;
#pragma unroll
    for (int p = 0; p < 2; p++) {   // A: 128 rows x 4 chunks of 16B
        int u = tid + p * 256;
        int row = u >> 2, c16 = u & 3;
        uint32_t d = st + tswz(row, c16);
        size_t goff = (size_t)(m0 + row) * HH + k0 + c16 * 8;
        CP16(d + A_HI_OFF, hh + goff);
        CP16(d + A_LO_OFF, hl + goff);
    }
#pragma unroll
    for (int p = 0; p < 2; p++) {   // B: 128 rows x 4 chunks of 16B
        int u = tid + p * 256;
        int row = u >> 2, c16 = u & 3;
        uint32_t d = st + tswz(row, c16);
        size_t goff = (size_t)(n0 + row) * HH + k0 + c16 * 8;
        CP16(d + B_HI_OFF, g_w_hi + goff);
        CP16(d + B_LO_OFF, g_w_lo + goff);
    }
}

__global__ __launch_bounds__(256, 2)
void lstm_step_mma(const float* __restrict__ out, int t) {
    extern __shared__ char smem[];
    float* x_s = (float*)(smem + XS_OFF);       // [128][2]
    int tid = threadIdx.x;
    int wid = tid >> 5, lane = tid & 31;
    int g = lane >> 2, tig = lane & 3;
    int wm = wid & 3, wn = wid >> 2;            // 4 m-warps x 2 n-warps
    int n0 = blockIdx.x * 128, m0 = blockIdx.y * 128;
    int src = t & 1, dst = src ^ 1;
    const __nv_bfloat16* hh = g_h_hi[src];
    const __nv_bfloat16* hl = g_h_lo[src];
    uint32_t sbase = smem_u32(smem + STAGE0);

    // ldmatrix lane mapping (logical row / 16B-chunk-within-kk), swizzle applied per kk
    int arow[2];
#pragma unroll
    for (int mi = 0; mi < 2; mi++) arow[mi] = wm * 32 + mi * 16 + (lane & 15);
    int abit = lane >> 4;                       // which 16B half of the kk-block
    int brow[4];
#pragma unroll
    for (int nip = 0; nip < 4; nip++)
        brow[nip] = wn * 64 + nip * 16 + ((lane >> 4) << 3) + (lane & 7);
    int bbit = (lane >> 3) & 1;

    uint32_t abase[2], asw[2], bbase[4], bsw[4];
#pragma unroll
    for (int mi = 0; mi < 2; mi++) { abase[mi] = arow[mi] * 64; asw[mi] = (arow[mi] >> 1) & 3; }
#pragma unroll
    for (int nip = 0; nip < 4; nip++) { bbase[nip] = brow[nip] * 64; bsw[nip] = (brow[nip] >> 1) & 3; }

    // prev coords -> smem
    if (tid < 128) {
        float x0 = 0.0f, x1 = 0.0f;
        if (t > 0) {
            x0 = out[((m0 + tid) * TT + t - 1) * 2 + 0];
            x1 = out[((m0 + tid) * TT + t - 1) * 2 + 1];
        }
        x_s[tid * 2 + 0] = x0;
        x_s[tid * 2 + 1] = x1;
    }

    float acc[2][8][4];
#pragma unroll
    for (int mi = 0; mi < 2; mi++)
#pragma unroll
        for (int ni = 0; ni < 8; ni++)
#pragma unroll
            for (int j = 0; j < 4; j++) acc[mi][ni][j] = 0.0f;

    load_chunk(sbase, 0, 0, m0, n0, hh, hl, tid);
    CP_COMMIT();
    load_chunk(sbase, 1, BKC, m0, n0, hh, hl, tid);
    CP_COMMIT();

    for (int c = 0; c < NCHUNK; c++) {
        if (c + 1 < NCHUNK) CP_WAITG(1); else CP_WAITG(0);   // chunk c arrived (this thread)
        __syncthreads();        // all threads' chunk-c data visible; stage (c+2)%3 no longer read
        if (c + 2 < NCHUNK) {
            load_chunk(sbase, (c + 2) % 3, (c + 2) * BKC, m0, n0, hh, hl, tid);
            CP_COMMIT();
        }

        uint32_t stage = sbase + (c % 3) * STAGE_BYTES;
#pragma unroll
        for (int kk = 0; kk < 2; kk++) {
            uint32_t ah[2][4], al[2][4];
#pragma unroll
            for (int mi = 0; mi < 2; mi++) {
                int cc = kk * 2 + abit;
                uint32_t ao = abase[mi] + (((cc ^ asw[mi]) & 3) << 4);
                LDSM4(ah[mi], stage + A_HI_OFF + ao);
                LDSM4(al[mi], stage + A_LO_OFF + ao);
            }
#pragma unroll
            for (int nip = 0; nip < 4; nip++) {
                int cc = kk * 2 + bbit;
                uint32_t bo = bbase[nip] + (((cc ^ bsw[nip]) & 3) << 4);
                uint32_t bh[4], bl[4];
                LDSM4(bh, stage + B_HI_OFF + bo);
                LDSM4(bl, stage + B_LO_OFF + bo);
#pragma unroll
                for (int ni2 = 0; ni2 < 2; ni2++)
#pragma unroll
                    for (int mi = 0; mi < 2; mi++)
                        mma16816(acc[mi][nip * 2 + ni2], ah[mi], bh + ni2 * 2);
#pragma unroll
                for (int ni2 = 0; ni2 < 2; ni2++)
#pragma unroll
                    for (int mi = 0; mi < 2; mi++)
                        mma16816(acc[mi][nip * 2 + ni2], ah[mi], bl + ni2 * 2);
#pragma unroll
                for (int ni2 = 0; ni2 < 2; ni2++)
#pragma unroll
                    for (int mi = 0; mi < 2; mi++)
                        mma16816(acc[mi][nip * 2 + ni2], al[mi], bh + ni2 * 2);
            }
        }
    }

    // ------------------------------ fused LSTM epilogue
#pragma unroll
    for (int mi = 0; mi < 2; mi++) {
        int r0 = wm * 32 + mi * 16 + g;
#pragma unroll
        for (int ni = 0; ni < 8; ni++) {
            float o0 = acc[mi][ni][0], o1 = acc[mi][ni][1];
            float o2 = acc[mi][ni][2], o3 = acc[mi][ni][3];
            float p0 = __shfl_xor_sync(0xFFFFFFFFu, o0, 1);
            float p1 = __shfl_xor_sync(0xFFFFFFFFu, o1, 1);
            float p2 = __shfl_xor_sync(0xFFFFFFFFu, o2, 1);
            float p3 = __shfl_xor_sync(0xFFFFFFFFu, o3, 1);
            if ((tig & 1) == 0) {
                int col = wn * 64 + ni * 8 + 2 * tig;
                int np = n0 + col;
                float4 bs = *(const float4*)&g_bsum[np];
                float4 wa = *(const float4*)&g_wih0[np];
                float4 wb = *(const float4*)&g_wih1[np];
                int hc = np >> 2;
#pragma unroll
                for (int rr = 0; rr < 2; rr++) {
                    int rl = r0 + rr * 8;
                    int m = m0 + rl;
                    float x0 = x_s[rl * 2 + 0], x1 = x_s[rl * 2 + 1];
                    float vi = rr ? o2 : o0, vf = rr ? o3 : o1;
                    float vg = rr ? p2 : p0, vo = rr ? p3 : p1;
                    float pi = vi + bs.x + x0 * wa.x + x1 * wb.x;
                    float pf = vf + bs.y + x0 * wa.y + x1 * wb.y;
                    float pg = vg + bs.z + x0 * wa.z + x1 * wb.z;
                    float po = vo + bs.w + x0 * wa.w + x1 * wb.w;
                    float cp = (t == 0) ? 0.0f : g_c[m * HH + hc];
                    float cn = fsigm(pf) * cp + fsigm(pi) * ftanh(pg);
                    g_c[m * HH + hc] = cn;
                    float h = fsigm(po) * ftanh(cn);
                    __nv_bfloat16 hi = __float2bfloat16_rn(h);
                    g_h_hi[dst][m * HH + hc] = hi;
                    g_h_lo[dst][m * HH + hc] = __float2bfloat16_rn(h - __bfloat162float(hi));
                }
            }
        }
    }
}

// ------------------------------------------------------------------ head (vectorized)
__global__ void head_kernel(const float* __restrict__ W_out, const float* __restrict__ b_out,
                            const float* __restrict__ W_stop, const float* __restrict__ b_stop,
                            float* __restrict__ out, int t) {
    int wid = threadIdx.x >> 5, lane = threadIdx.x & 31;
    int b = blockIdx.x * 8 + wid;
    const uint4* hh4 = (const uint4*)(g_h_hi[(t & 1) ^ 1] + b * HH);
    const uint4* hl4 = (const uint4*)(g_h_lo[(t & 1) ^ 1] + b * HH);

    float s0 = 0.0f, s1 = 0.0f, ss = 0.0f;
#pragma unroll
    for (int it = 0; it < 8; it++) {
        int v = it * 32 + lane;
        uint4 vh = hh4[v], vl = hl4[v];
        int e = v * 8;
#pragma unroll
        for (int w = 0; w < 4; w++) {
            uint32_t uh = (&vh.x)[w], ul = (&vl.x)[w];
            float2 fh = __bfloat1622float2(*(__nv_bfloat162*)&uh);
            float2 fl = __bfloat1622float2(*(__nv_bfloat162*)&ul);
            float h0 = fh.x + fl.x, h1 = fh.y + fl.y;
            int i = e + w * 2;
            float2 w0 = *(const float2*)&W_out[i];
            float2 w1 = *(const float2*)&W_out[HH + i];
            float2 wsv = *(const float2*)&W_stop[i];
            s0 += h0 * w0.x + h1 * w0.y;
            s1 += h0 * w1.x + h1 * w1.y;
            ss += h0 * wsv.x + h1 * wsv.y;
        }
    }
#pragma unroll
    for (int o = 16; o > 0; o >>= 1) {
        s0 += __shfl_down_sync(0xFFFFFFFFu, s0, o);
        s1 += __shfl_down_sync(0xFFFFFFFFu, s1, o);
        ss += __shfl_down_sync(0xFFFFFFFFu, ss, o);
    }
    if (lane == 0) {
        out[(b * TT + t) * 2 + 0] = s0 + b_out[0];
        out[(b * TT + t) * 2 + 1] = s1 + b_out[1];
        out[BB * TT * 2 + b * TT + t] = fsigm(ss + b_stop[0]);
    }
}

// ------------------------------------------------------------------ launch
extern "C" void kernel_launch(void* const* d_in, const int* in_sizes, int n_in,
                              void* d_out, int out_size) {
    const float* emb     = (const float*)d_in[0];
    const float* W_embed = (const float*)d_in[2];
    const float* b_embed = (const float*)d_in[3];
    const float* W_ih    = (const float*)d_in[4];
    const float* b_ih    = (const float*)d_in[5];
    const float* W_hh    = (const float*)d_in[6];
    const float* b_hh    = (const float*)d_in[7];
    const float* W_out   = (const float*)d_in[8];
    const float* b_out   = (const float*)d_in[9];
    const float* W_stop  = (const float*)d_in[10];
    const float* b_stop  = (const float*)d_in[11];
    float* out = (float*)d_out;

    cudaFuncSetAttribute(lstm_step_mma, cudaFuncAttributeMaxDynamicSharedMemorySize, SMEM_TOTAL);

    prep_w_kernel<<<NG, 256>>>(W_hh);
    prep_misc_kernel<<<NG / 256, 256>>>(b_ih, b_hh, W_ih);
    h0_kernel<<<dim3(HH / 64, BB / 64), 256>>>(emb, W_embed, b_embed);

    for (int t = 0; t < TT; t++) {
        lstm_step_mma<<<dim3(64, 4), 256, SMEM_TOTAL>>>(out, t);
        head_kernel<<<64, 256>>>(W_out, b_out, W_stop, b_stop, out, t);
    }
}

// round 7
// speedup vs baseline: 1.5183x; 1.3383x over previous
#include <cuda_runtime.h>
#include <cuda_fp16.h>
#include <math.h>
#include <cstdint>

#define BB 512
#define HH 2048
#define EE 2048
#define TT 256
#define NG 8192    // 4*H, permuted: n' = hc*4 + gate (i,f,g,o)

// ------------------------------------------------------------------ state
__device__ __align__(128) __half g_h[2][BB * HH];      // fp16 A operand (ping-pong)
__device__ __align__(128) float  g_hf[BB * HH];        // fp32 h for head
__device__ __align__(128) float  g_c[BB * HH];
__device__ __align__(128) __half g_w_hi[NG * HH];
__device__ __align__(128) __half g_w_lo[NG * HH];
__device__ __align__(128) float  g_bsum[NG];
__device__ __align__(128) float  g_wih0[NG];
__device__ __align__(128) float  g_wih1[NG];

// ------------------------------------------------------------------ helpers
#define CP16(dst, src)  asm volatile("cp.async.cg.shared.global [%0], [%1], 16;" :: "r"(dst), "l"(src))
#define CP_COMMIT()     asm volatile("cp.async.commit_group;" ::: "memory")
#define CP_WAITG(n)     asm volatile("cp.async.wait_group %0;" :: "n"(n) : "memory")

#define LDSM4(r, a) \
    asm volatile("ldmatrix.sync.aligned.m8n8.x4.shared.b16 {%0,%1,%2,%3}, [%4];" \
        : "=r"((r)[0]), "=r"((r)[1]), "=r"((r)[2]), "=r"((r)[3]) : "r"(a))

__device__ __forceinline__ uint32_t smem_u32(const void* p) {
    uint32_t a;
    asm("{ .reg .u64 t; cvta.to.shared.u64 t, %1; cvt.u32.u64 %0, t; }" : "=r"(a) : "l"(p));
    return a;
}

__device__ __forceinline__ void mma16816(float* d, const uint32_t* a, const uint32_t* b) {
    asm volatile(
        "mma.sync.aligned.m16n8k16.row.col.f32.f16.f16.f32 "
        "{%0,%1,%2,%3}, {%4,%5,%6,%7}, {%8,%9}, {%0,%1,%2,%3};"
        : "+f"(d[0]), "+f"(d[1]), "+f"(d[2]), "+f"(d[3])
        : "r"(a[0]), "r"(a[1]), "r"(a[2]), "r"(a[3]), "r"(b[0]), "r"(b[1]));
}

__device__ __forceinline__ float fsigm(float x) { return 1.0f / (1.0f + __expf(-x)); }
__device__ __forceinline__ float ftanh(float x) {
    if (x > 8.0f) return 1.0f;
    if (x < -8.0f) return -1.0f;
    float e = __expf(2.0f * x);
    return (e - 1.0f) / (e + 1.0f);
}

// swizzled 64B-row tile: phys(row, c16) = row*64 + ((c16 ^ ((row>>1)&3))<<4)
__device__ __forceinline__ uint32_t tswz(int row, int c16) {
    return (uint32_t)(row * 64 + (((c16 ^ ((row >> 1) & 3)) & 3) << 4));
}

// ------------------------------------------------------------------ prep
__global__ void prep_w_kernel(const float* __restrict__ W_hh) {
    int np = blockIdx.x;                 // 0..NG-1
    int g = np & 3, hc = np >> 2;
    const float* src = W_hh + (size_t)(g * HH + hc) * HH;
    __half* dh = g_w_hi + (size_t)np * HH;
    __half* dl = g_w_lo + (size_t)np * HH;
#pragma unroll
    for (int j = 0; j < HH / 256; j++) {
        int k = threadIdx.x + j * 256;
        float w = src[k];
        __half hi = __float2half_rn(w);
        dh[k] = hi;
        dl[k] = __float2half_rn(w - __half2float(hi));
    }
}

__global__ void prep_misc_kernel(const float* __restrict__ b_ih, const float* __restrict__ b_hh,
                                 const float* __restrict__ W_ih) {
    int np = blockIdx.x * 256 + threadIdx.x;
    int g = np & 3, hc = np >> 2;
    int j = g * HH + hc;
    g_bsum[np] = b_ih[j] + b_hh[j];
    g_wih0[np] = W_ih[2 * j + 0];
    g_wih1[np] = W_ih[2 * j + 1];
}

// ------------------------------------------------------------------ h0 (fp32 SIMT, one-time)
#define KC 16
__global__ __launch_bounds__(256, 2)
void h0_kernel(const float* __restrict__ emb, const float* __restrict__ W,
               const float* __restrict__ bias) {
    __shared__ float As[KC][64];
    __shared__ float Bs[KC][64];
    int tid = threadIdx.x;
    int m0 = blockIdx.y * 64, n0 = blockIdx.x * 64;
    int lrow = tid >> 2, lk4 = (tid & 3) * 4;
    int tx_m = tid >> 4, tx_n = tid & 15;

    float acc[4][4];
#pragma unroll
    for (int i = 0; i < 4; i++)
#pragma unroll
        for (int j = 0; j < 4; j++) acc[i][j] = 0.0f;

    for (int k0 = 0; k0 < EE; k0 += KC) {
        float4 av = *(const float4*)&emb[(m0 + lrow) * EE + k0 + lk4];
        float4 bv = *(const float4*)&W[(n0 + lrow) * EE + k0 + lk4];
        __syncthreads();
        As[lk4 + 0][lrow] = av.x; As[lk4 + 1][lrow] = av.y;
        As[lk4 + 2][lrow] = av.z; As[lk4 + 3][lrow] = av.w;
        Bs[lk4 + 0][lrow] = bv.x; Bs[lk4 + 1][lrow] = bv.y;
        Bs[lk4 + 2][lrow] = bv.z; Bs[lk4 + 3][lrow] = bv.w;
        __syncthreads();
#pragma unroll
        for (int kk = 0; kk < KC; kk++) {
            float a[4], b[4];
            *(float4*)a = *(float4*)&As[kk][tx_m * 4];
            *(float4*)b = *(float4*)&Bs[kk][tx_n * 4];
#pragma unroll
            for (int mi = 0; mi < 4; mi++)
#pragma unroll
                for (int ni = 0; ni < 4; ni++) acc[mi][ni] += a[mi] * b[ni];
        }
    }
#pragma unroll
    for (int mi = 0; mi < 4; mi++) {
        int m = m0 + tx_m * 4 + mi;
#pragma unroll
        for (int ni = 0; ni < 4; ni++) {
            int n = n0 + tx_n * 4 + ni;
            float h = acc[mi][ni] + bias[n];
            g_h[0][m * HH + n] = __float2half_rn(h);
        }
    }
}

// ------------------------------------------------------------------ main LSTM step
// CTA tile: 128 M x 128 N, 256 threads = 8 warps (4 m x 2 n of 32x64).
// Grid (64, 4) = 256 CTAs, 2 CTAs/SM. fp16 2-pass: A single, W hi/lo.
#define BKC 32           // K per chunk
#define NCHUNK 64        // 2048 / 32
#define A_OFF    0
#define B_HI_OFF 8192
#define B_LO_OFF 16384
#define STAGE_BYTES 24576
#define XS_OFF 0
#define STAGE0 1024
#define SMEM_TOTAL (STAGE0 + 3 * STAGE_BYTES)

__device__ __forceinline__ void load_chunk(uint32_t sbase, int stage_idx, int k0, int m0, int n0,
                                           const __half* hsrc, int tid) {
    uint32_t st = sbase + stage_idx * STAGE_BYTES;
#pragma unroll
    for (int p = 0; p < 2; p++) {   // A: 128 rows x 4 chunks of 16B (single type)
        int u = tid + p * 256;
        int row = u >> 2, c16 = u & 3;
        uint32_t d = st + tswz(row, c16);
        size_t goff = (size_t)(m0 + row) * HH + k0 + c16 * 8;
        CP16(d + A_OFF, hsrc + goff);
    }
#pragma unroll
    for (int p = 0; p < 2; p++) {   // B: 128 rows x 4 chunks of 16B, hi+lo
        int u = tid + p * 256;
        int row = u >> 2, c16 = u & 3;
        uint32_t d = st + tswz(row, c16);
        size_t goff = (size_t)(n0 + row) * HH + k0 + c16 * 8;
        CP16(d + B_HI_OFF, g_w_hi + goff);
        CP16(d + B_LO_OFF, g_w_lo + goff);
    }
}

__global__ __launch_bounds__(256, 2)
void lstm_step_mma(const float* __restrict__ out, int t) {
    extern __shared__ char smem[];
    float* x_s = (float*)(smem + XS_OFF);       // [128][2]
    int tid = threadIdx.x;
    int wid = tid >> 5, lane = tid & 31;
    int g = lane >> 2, tig = lane & 3;
    int wm = wid & 3, wn = wid >> 2;            // 4 m-warps x 2 n-warps
    int n0 = blockIdx.x * 128, m0 = blockIdx.y * 128;
    int src = t & 1, dst = src ^ 1;
    const __half* hsrc = g_h[src];
    uint32_t sbase = smem_u32(smem + STAGE0);

    // ldmatrix lane mapping
    int arow[2];
#pragma unroll
    for (int mi = 0; mi < 2; mi++) arow[mi] = wm * 32 + mi * 16 + (lane & 15);
    int abit = lane >> 4;
    int brow[4];
#pragma unroll
    for (int nip = 0; nip < 4; nip++)
        brow[nip] = wn * 64 + nip * 16 + ((lane >> 4) << 3) + (lane & 7);
    int bbit = (lane >> 3) & 1;

    uint32_t abase[2], asw[2], bbase[4], bsw[4];
#pragma unroll
    for (int mi = 0; mi < 2; mi++) { abase[mi] = arow[mi] * 64; asw[mi] = (arow[mi] >> 1) & 3; }
#pragma unroll
    for (int nip = 0; nip < 4; nip++) { bbase[nip] = brow[nip] * 64; bsw[nip] = (brow[nip] >> 1) & 3; }

    // prev coords -> smem
    if (tid < 128) {
        float x0 = 0.0f, x1 = 0.0f;
        if (t > 0) {
            x0 = out[((m0 + tid) * TT + t - 1) * 2 + 0];
            x1 = out[((m0 + tid) * TT + t - 1) * 2 + 1];
        }
        x_s[tid * 2 + 0] = x0;
        x_s[tid * 2 + 1] = x1;
    }

    float acc[2][8][4];
#pragma unroll
    for (int mi = 0; mi < 2; mi++)
#pragma unroll
        for (int ni = 0; ni < 8; ni++)
#pragma unroll
            for (int j = 0; j < 4; j++) acc[mi][ni][j] = 0.0f;

    load_chunk(sbase, 0, 0, m0, n0, hsrc, tid);
    CP_COMMIT();
    load_chunk(sbase, 1, BKC, m0, n0, hsrc, tid);
    CP_COMMIT();

    for (int c = 0; c < NCHUNK; c++) {
        if (c + 1 < NCHUNK) CP_WAITG(1); else CP_WAITG(0);
        __syncthreads();        // chunk c visible; stage (c+2)%3 free
        if (c + 2 < NCHUNK) {
            load_chunk(sbase, (c + 2) % 3, (c + 2) * BKC, m0, n0, hsrc, tid);
            CP_COMMIT();
        }

        uint32_t stage = sbase + (c % 3) * STAGE_BYTES;
#pragma unroll
        for (int kk = 0; kk < 2; kk++) {
            uint32_t ah[2][4];
#pragma unroll
            for (int mi = 0; mi < 2; mi++) {
                int cc = kk * 2 + abit;
                uint32_t ao = abase[mi] + (((cc ^ asw[mi]) & 3) << 4);
                LDSM4(ah[mi], stage + A_OFF + ao);
            }
#pragma unroll
            for (int nip = 0; nip < 4; nip++) {
                int cc = kk * 2 + bbit;
                uint32_t bo = bbase[nip] + (((cc ^ bsw[nip]) & 3) << 4);
                uint32_t bh[4], bl[4];
                LDSM4(bh, stage + B_HI_OFF + bo);
                LDSM4(bl, stage + B_LO_OFF + bo);
#pragma unroll
                for (int ni2 = 0; ni2 < 2; ni2++)
#pragma unroll
                    for (int mi = 0; mi < 2; mi++)
                        mma16816(acc[mi][nip * 2 + ni2], ah[mi], bh + ni2 * 2);
#pragma unroll
                for (int ni2 = 0; ni2 < 2; ni2++)
#pragma unroll
                    for (int mi = 0; mi < 2; mi++)
                        mma16816(acc[mi][nip * 2 + ni2], ah[mi], bl + ni2 * 2);
            }
        }
    }

    // ------------------------------ fused LSTM epilogue
#pragma unroll
    for (int mi = 0; mi < 2; mi++) {
        int r0 = wm * 32 + mi * 16 + g;
#pragma unroll
        for (int ni = 0; ni < 8; ni++) {
            float o0 = acc[mi][ni][0], o1 = acc[mi][ni][1];
            float o2 = acc[mi][ni][2], o3 = acc[mi][ni][3];
            float p0 = __shfl_xor_sync(0xFFFFFFFFu, o0, 1);
            float p1 = __shfl_xor_sync(0xFFFFFFFFu, o1, 1);
            float p2 = __shfl_xor_sync(0xFFFFFFFFu, o2, 1);
            float p3 = __shfl_xor_sync(0xFFFFFFFFu, o3, 1);
            if ((tig & 1) == 0) {
                int col = wn * 64 + ni * 8 + 2 * tig;
                int np = n0 + col;
                float4 bs = *(const float4*)&g_bsum[np];
                float4 wa = *(const float4*)&g_wih0[np];
                float4 wb = *(const float4*)&g_wih1[np];
                int hc = np >> 2;
#pragma unroll
                for (int rr = 0; rr < 2; rr++) {
                    int rl = r0 + rr * 8;
                    int m = m0 + rl;
                    float x0 = x_s[rl * 2 + 0], x1 = x_s[rl * 2 + 1];
                    float vi = rr ? o2 : o0, vf = rr ? o3 : o1;
                    float vg = rr ? p2 : p0, vo = rr ? p3 : p1;
                    float pi = vi + bs.x + x0 * wa.x + x1 * wb.x;
                    float pf = vf + bs.y + x0 * wa.y + x1 * wb.y;
                    float pg = vg + bs.z + x0 * wa.z + x1 * wb.z;
                    float po = vo + bs.w + x0 * wa.w + x1 * wb.w;
                    float cp = (t == 0) ? 0.0f : g_c[m * HH + hc];
                    float cn = fsigm(pf) * cp + fsigm(pi) * ftanh(pg);
                    g_c[m * HH + hc] = cn;
                    float h = fsigm(po) * ftanh(cn);
                    g_h[dst][m * HH + hc] = __float2half_rn(h);
                    g_hf[m * HH + hc] = h;
                }
            }
        }
    }
}

// ------------------------------------------------------------------ head (fp32 h, vectorized)
__global__ void head_kernel(const float* __restrict__ W_out, const float* __restrict__ b_out,
                            const float* __restrict__ W_stop, const float* __restrict__ b_stop,
                            float* __restrict__ out, int t) {
    int wid = threadIdx.x >> 5, lane = threadIdx.x & 31;
    int b = blockIdx.x * 8 + wid;
    const float4* h4 = (const float4*)(g_hf + b * HH);

    float s0 = 0.0f, s1 = 0.0f, ss = 0.0f;
#pragma unroll
    for (int it = 0; it < 16; it++) {
        int v = it * 32 + lane;           // float4 index: 4 floats each
        float4 hv = h4[v];
        int i = v * 4;
        float4 w0 = *(const float4*)&W_out[i];
        float4 w1 = *(const float4*)&W_out[HH + i];
        float4 wsv = *(const float4*)&W_stop[i];
        s0 += hv.x * w0.x + hv.y * w0.y + hv.z * w0.z + hv.w * w0.w;
        s1 += hv.x * w1.x + hv.y * w1.y + hv.z * w1.z + hv.w * w1.w;
        ss += hv.x * wsv.x + hv.y * wsv.y + hv.z * wsv.z + hv.w * wsv.w;
    }
#pragma unroll
    for (int o = 16; o > 0; o >>= 1) {
        s0 += __shfl_down_sync(0xFFFFFFFFu, s0, o);
        s1 += __shfl_down_sync(0xFFFFFFFFu, s1, o);
        ss += __shfl_down_sync(0xFFFFFFFFu, ss, o);
    }
    if (lane == 0) {
        out[(b * TT + t) * 2 + 0] = s0 + b_out[0];
        out[(b * TT + t) * 2 + 1] = s1 + b_out[1];
        out[BB * TT * 2 + b * TT + t] = fsigm(ss + b_stop[0]);
    }
}

// ------------------------------------------------------------------ launch
extern "C" void kernel_launch(void* const* d_in, const int* in_sizes, int n_in,
                              void* d_out, int out_size) {
    const float* emb     = (const float*)d_in[0];
    const float* W_embed = (const float*)d_in[2];
    const float* b_embed = (const float*)d_in[3];
    const float* W_ih    = (const float*)d_in[4];
    const float* b_ih    = (const float*)d_in[5];
    const float* W_hh    = (const float*)d_in[6];
    const float* b_hh    = (const float*)d_in[7];
    const float* W_out   = (const float*)d_in[8];
    const float* b_out   = (const float*)d_in[9];
    const float* W_stop  = (const float*)d_in[10];
    const float* b_stop  = (const float*)d_in[11];
    float* out = (float*)d_out;

    cudaFuncSetAttribute(lstm_step_mma, cudaFuncAttributeMaxDynamicSharedMemorySize, SMEM_TOTAL);

    prep_w_kernel<<<NG, 256>>>(W_hh);
    prep_misc_kernel<<<NG / 256, 256>>>(b_ih, b_hh, W_ih);
    h0_kernel<<<dim3(HH / 64, BB / 64), 256>>>(emb, W_embed, b_embed);

    for (int t = 0; t < TT; t++) {
        lstm_step_mma<<<dim3(64, 4), 256, SMEM_TOTAL>>>(out, t);
        head_kernel<<<64, 256>>>(W_out, b_out, W_stop, b_stop, out, t);
    }
}

// round 8
// speedup vs baseline: 1.6531x; 1.0888x over previous
#include <cuda_runtime.h>
#include <cuda_fp16.h>
#include <math.h>
#include <cstdint>

#define BB 512
#define HH 2048
#define EE 2048
#define TT 256
#define NG 8192    // 4*H, permuted: n' = hc*4 + gate (i,f,g,o)

// ------------------------------------------------------------------ state
__device__ __align__(128) __half g_h[2][BB * HH];      // fp16 A operand (ping-pong)
__device__ __align__(128) float  g_c[BB * HH];
__device__ __align__(128) __half g_w_hi[NG * HH];
__device__ __align__(128) __half g_w_lo[NG * HH];
__device__ __align__(128) float  g_bsum[NG];
__device__ __align__(128) float  g_wih0[NG];
__device__ __align__(128) float  g_wih1[NG];

// ------------------------------------------------------------------ helpers
#define CP16(dst, src)  asm volatile("cp.async.cg.shared.global [%0], [%1], 16;" :: "r"(dst), "l"(src))
#define CP_COMMIT()     asm volatile("cp.async.commit_group;" ::: "memory")
#define CP_WAIT0()      asm volatile("cp.async.wait_group 0;" ::: "memory")

#define LDSM4(r, a) \
    asm volatile("ldmatrix.sync.aligned.m8n8.x4.shared.b16 {%0,%1,%2,%3}, [%4];" \
        : "=r"((r)[0]), "=r"((r)[1]), "=r"((r)[2]), "=r"((r)[3]) : "r"(a))

__device__ __forceinline__ uint32_t smem_u32(const void* p) {
    uint32_t a;
    asm("{ .reg .u64 t; cvta.to.shared.u64 t, %1; cvt.u32.u64 %0, t; }" : "=r"(a) : "l"(p));
    return a;
}

__device__ __forceinline__ void mma16816(float* d, const uint32_t* a, const uint32_t* b) {
    asm volatile(
        "mma.sync.aligned.m16n8k16.row.col.f32.f16.f16.f32 "
        "{%0,%1,%2,%3}, {%4,%5,%6,%7}, {%8,%9}, {%0,%1,%2,%3};"
        : "+f"(d[0]), "+f"(d[1]), "+f"(d[2]), "+f"(d[3])
        : "r"(a[0]), "r"(a[1]), "r"(a[2]), "r"(a[3]), "r"(b[0]), "r"(b[1]));
}

__device__ __forceinline__ float fsigm(float x) { return 1.0f / (1.0f + __expf(-x)); }
__device__ __forceinline__ float ftanh(float x) {
    if (x > 8.0f) return 1.0f;
    if (x < -8.0f) return -1.0f;
    float e = __expf(2.0f * x);
    return (e - 1.0f) / (e + 1.0f);
}

// 128B-row swizzle: phys = row*128 + ((c8 ^ (row&7))<<4), c8 in 0..7
__device__ __forceinline__ uint32_t swz128(int row, int c8) {
    return (uint32_t)(row * 128 + (((c8 ^ (row & 7)) & 7) << 4));
}

// ------------------------------------------------------------------ prep
__global__ void prep_w_kernel(const float* __restrict__ W_hh) {
    int np = blockIdx.x;                 // 0..NG-1
    int g = np & 3, hc = np >> 2;
    const float* src = W_hh + (size_t)(g * HH + hc) * HH;
    __half* dh = g_w_hi + (size_t)np * HH;
    __half* dl = g_w_lo + (size_t)np * HH;
#pragma unroll
    for (int j = 0; j < HH / 256; j++) {
        int k = threadIdx.x + j * 256;
        float w = src[k];
        __half hi = __float2half_rn(w);
        dh[k] = hi;
        dl[k] = __float2half_rn(w - __half2float(hi));
    }
}

__global__ void prep_misc_kernel(const float* __restrict__ b_ih, const float* __restrict__ b_hh,
                                 const float* __restrict__ W_ih) {
    int np = blockIdx.x * 256 + threadIdx.x;
    int g = np & 3, hc = np >> 2;
    int j = g * HH + hc;
    g_bsum[np] = b_ih[j] + b_hh[j];
    g_wih0[np] = W_ih[2 * j + 0];
    g_wih1[np] = W_ih[2 * j + 1];
}

__global__ void zero_out_kernel(float* __restrict__ out) {
    int i = blockIdx.x * 256 + threadIdx.x;
    if (i < BB * TT * 3) out[i] = 0.0f;
}

__global__ void stop_final_kernel(float* __restrict__ out, const float* __restrict__ b_stop) {
    int i = blockIdx.x * 256 + threadIdx.x;
    if (i < BB * TT) {
        float v = out[BB * TT * 2 + i];
        out[BB * TT * 2 + i] = fsigm(v + b_stop[0]);
    }
}

// ------------------------------------------------------------------ h0 (fp32 SIMT, one-time)
#define KC 16
__global__ __launch_bounds__(256, 2)
void h0_kernel(const float* __restrict__ emb, const float* __restrict__ W,
               const float* __restrict__ bias) {
    __shared__ float As[KC][64];
    __shared__ float Bs[KC][64];
    int tid = threadIdx.x;
    int m0 = blockIdx.y * 64, n0 = blockIdx.x * 64;
    int lrow = tid >> 2, lk4 = (tid & 3) * 4;
    int tx_m = tid >> 4, tx_n = tid & 15;

    float acc[4][4];
#pragma unroll
    for (int i = 0; i < 4; i++)
#pragma unroll
        for (int j = 0; j < 4; j++) acc[i][j] = 0.0f;

    for (int k0 = 0; k0 < EE; k0 += KC) {
        float4 av = *(const float4*)&emb[(m0 + lrow) * EE + k0 + lk4];
        float4 bv = *(const float4*)&W[(n0 + lrow) * EE + k0 + lk4];
        __syncthreads();
        As[lk4 + 0][lrow] = av.x; As[lk4 + 1][lrow] = av.y;
        As[lk4 + 2][lrow] = av.z; As[lk4 + 3][lrow] = av.w;
        Bs[lk4 + 0][lrow] = bv.x; Bs[lk4 + 1][lrow] = bv.y;
        Bs[lk4 + 2][lrow] = bv.z; Bs[lk4 + 3][lrow] = bv.w;
        __syncthreads();
#pragma unroll
        for (int kk = 0; kk < KC; kk++) {
            float a[4], b[4];
            *(float4*)a = *(float4*)&As[kk][tx_m * 4];
            *(float4*)b = *(float4*)&Bs[kk][tx_n * 4];
#pragma unroll
            for (int mi = 0; mi < 4; mi++)
#pragma unroll
                for (int ni = 0; ni < 4; ni++) acc[mi][ni] += a[mi] * b[ni];
        }
    }
#pragma unroll
    for (int mi = 0; mi < 4; mi++) {
        int m = m0 + tx_m * 4 + mi;
#pragma unroll
        for (int ni = 0; ni < 4; ni++) {
            int n = n0 + tx_n * 4 + ni;
            float h = acc[mi][ni] + bias[n];
            g_h[0][m * HH + n] = __float2half_rn(h);
        }
    }
}

// ------------------------------------------------------------------ main LSTM step
// CTA tile: 128 M x 128 N, 256 threads = 8 warps (2 m x 4 n of 64x32).
// Grid (64, 4) = 256 CTAs, 2 CTAs/SM. BKC=64, 2-stage, 1 sync/chunk.
// Head fused: partial dots -> smem reduce -> global atomicAdd.
#define BKC 64
#define NCHUNK 32        // 2048 / 64
#define A_OFF    0
#define B_HI_OFF 16384
#define B_LO_OFF 32768
#define STAGE_BYTES 49152
#define XS_OFF   0       // 128*2 floats = 1024
#define SRED_OFF 1024    // 128*4 floats = 2048
#define WH_OFF   3072    // 3*32 floats = 384
#define STAGE0   4096
#define SMEM_TOTAL (STAGE0 + 2 * STAGE_BYTES)

__device__ __forceinline__ void load_chunk(uint32_t sbase, int stage_idx, int k0, int m0, int n0,
                                           const __half* hsrc, int tid) {
    uint32_t st = sbase + stage_idx * STAGE_BYTES;
#pragma unroll
    for (int p = 0; p < 4; p++) {   // A: 128 rows x 8 chunks of 16B
        int u = tid + p * 256;
        int row = u >> 3, c8 = u & 7;
        uint32_t d = st + swz128(row, c8);
        size_t goff = (size_t)(m0 + row) * HH + k0 + c8 * 8;
        CP16(d + A_OFF, hsrc + goff);
    }
#pragma unroll
    for (int p = 0; p < 4; p++) {   // B: 128 rows x 8 chunks of 16B, hi+lo
        int u = tid + p * 256;
        int row = u >> 3, c8 = u & 7;
        uint32_t d = st + swz128(row, c8);
        size_t goff = (size_t)(n0 + row) * HH + k0 + c8 * 8;
        CP16(d + B_HI_OFF, g_w_hi + goff);
        CP16(d + B_LO_OFF, g_w_lo + goff);
    }
}

__global__ __launch_bounds__(256, 2)
void lstm_step_mma(float* __restrict__ out, int t,
                   const float* __restrict__ W_out, const float* __restrict__ W_stop,
                   const float* __restrict__ b_out) {
    extern __shared__ char smem[];
    float* x_s  = (float*)(smem + XS_OFF);     // [128][2]
    float* sred = (float*)(smem + SRED_OFF);   // [128][4]
    float* w_s0 = (float*)(smem + WH_OFF);     // [32]
    float* w_s1 = w_s0 + 32;
    float* w_ss = w_s0 + 64;
    int tid = threadIdx.x;
    int wid = tid >> 5, lane = tid & 31;
    int g = lane >> 2, tig = lane & 3;
    int wm = wid & 1, wn = wid >> 1;            // 2 m-warps x 4 n-warps
    int n0 = blockIdx.x * 128, m0 = blockIdx.y * 128;
    int src = t & 1, dst = src ^ 1;
    const __half* hsrc = g_h[src];
    uint32_t sbase = smem_u32(smem + STAGE0);

    // ldmatrix lane mapping: A 4 m-frags (64 rows), B 2 frag-pairs (32 cols)
    int arow[4];
#pragma unroll
    for (int mi = 0; mi < 4; mi++) arow[mi] = wm * 64 + mi * 16 + (lane & 15);
    int abit = lane >> 4;
    int brow[2];
#pragma unroll
    for (int nip = 0; nip < 2; nip++)
        brow[nip] = wn * 32 + nip * 16 + ((lane >> 4) << 3) + (lane & 7);
    int bbit = (lane >> 3) & 1;

    uint32_t abase[4], asw[4], bbase[2], bsw[2];
#pragma unroll
    for (int mi = 0; mi < 4; mi++) { abase[mi] = arow[mi] * 128; asw[mi] = arow[mi] & 7; }
#pragma unroll
    for (int nip = 0; nip < 2; nip++) { bbase[nip] = brow[nip] * 128; bsw[nip] = brow[nip] & 7; }

    // preload: prev coords, head weights, zero reduction buffer
    if (tid < 128) {
        float x0 = 0.0f, x1 = 0.0f;
        if (t > 0) {
            x0 = out[((m0 + tid) * TT + t - 1) * 2 + 0];
            x1 = out[((m0 + tid) * TT + t - 1) * 2 + 1];
        }
        x_s[tid * 2 + 0] = x0;
        x_s[tid * 2 + 1] = x1;
        sred[tid * 4 + 0] = 0.0f;
        sred[tid * 4 + 1] = 0.0f;
        sred[tid * 4 + 2] = 0.0f;
    }
    if (tid < 32) {
        int hc = (n0 >> 2) + tid;
        w_s0[tid] = W_out[hc];
        w_s1[tid] = W_out[HH + hc];
        w_ss[tid] = W_stop[hc];
    }

    float acc[4][4][4];
#pragma unroll
    for (int mi = 0; mi < 4; mi++)
#pragma unroll
        for (int ni = 0; ni < 4; ni++)
#pragma unroll
            for (int j = 0; j < 4; j++) acc[mi][ni][j] = 0.0f;

    load_chunk(sbase, 0, 0, m0, n0, hsrc, tid);
    CP_COMMIT();

    for (int c = 0; c < NCHUNK; c++) {
        CP_WAIT0();             // chunk c arrived (issued previous iteration)
        __syncthreads();        // c visible everywhere; all warps done with chunk c-1
        if (c + 1 < NCHUNK) {
            load_chunk(sbase, (c + 1) & 1, (c + 1) * BKC, m0, n0, hsrc, tid);
            CP_COMMIT();
        }

        uint32_t stage = sbase + (c & 1) * STAGE_BYTES;
#pragma unroll
        for (int kk = 0; kk < 4; kk++) {
            uint32_t ah[4][4];
#pragma unroll
            for (int mi = 0; mi < 4; mi++) {
                int cc = kk * 2 + abit;
                uint32_t ao = abase[mi] + (((cc ^ asw[mi]) & 7) << 4);
                LDSM4(ah[mi], stage + A_OFF + ao);
            }
#pragma unroll
            for (int nip = 0; nip < 2; nip++) {
                int cc = kk * 2 + bbit;
                uint32_t bo = bbase[nip] + (((cc ^ bsw[nip]) & 7) << 4);
                uint32_t bh[4], bl[4];
                LDSM4(bh, stage + B_HI_OFF + bo);
                LDSM4(bl, stage + B_LO_OFF + bo);
#pragma unroll
                for (int ni2 = 0; ni2 < 2; ni2++)
#pragma unroll
                    for (int mi = 0; mi < 4; mi++)
                        mma16816(acc[mi][nip * 2 + ni2], ah[mi], bh + ni2 * 2);
#pragma unroll
                for (int ni2 = 0; ni2 < 2; ni2++)
#pragma unroll
                    for (int mi = 0; mi < 4; mi++)
                        mma16816(acc[mi][nip * 2 + ni2], ah[mi], bl + ni2 * 2);
            }
        }
    }

    // ------------------------------ fused LSTM epilogue + head partials
#pragma unroll
    for (int mi = 0; mi < 4; mi++) {
        int r0 = wm * 64 + mi * 16 + g;
        float hs[2][3] = {{0.0f, 0.0f, 0.0f}, {0.0f, 0.0f, 0.0f}};
#pragma unroll
        for (int ni = 0; ni < 4; ni++) {
            float o0 = acc[mi][ni][0], o1 = acc[mi][ni][1];
            float o2 = acc[mi][ni][2], o3 = acc[mi][ni][3];
            float p0 = __shfl_xor_sync(0xFFFFFFFFu, o0, 1);
            float p1 = __shfl_xor_sync(0xFFFFFFFFu, o1, 1);
            float p2 = __shfl_xor_sync(0xFFFFFFFFu, o2, 1);
            float p3 = __shfl_xor_sync(0xFFFFFFFFu, o3, 1);
            if ((tig & 1) == 0) {
                int col = wn * 32 + ni * 8 + 2 * tig;
                int np = n0 + col;
                float4 bs = *(const float4*)&g_bsum[np];
                float4 wa = *(const float4*)&g_wih0[np];
                float4 wb = *(const float4*)&g_wih1[np];
                int hc = np >> 2;
                int hcl = col >> 2;
                float w0v = w_s0[hcl], w1v = w_s1[hcl], wsv = w_ss[hcl];
#pragma unroll
                for (int rr = 0; rr < 2; rr++) {
                    int rl = r0 + rr * 8;
                    int m = m0 + rl;
                    float x0 = x_s[rl * 2 + 0], x1 = x_s[rl * 2 + 1];
                    float vi = rr ? o2 : o0, vf = rr ? o3 : o1;
                    float vg = rr ? p2 : p0, vo = rr ? p3 : p1;
                    float pi = vi + bs.x + x0 * wa.x + x1 * wb.x;
                    float pf = vf + bs.y + x0 * wa.y + x1 * wb.y;
                    float pg = vg + bs.z + x0 * wa.z + x1 * wb.z;
                    float po = vo + bs.w + x0 * wa.w + x1 * wb.w;
                    float cp = (t == 0) ? 0.0f : g_c[m * HH + hc];
                    float cn = fsigm(pf) * cp + fsigm(pi) * ftanh(pg);
                    g_c[m * HH + hc] = cn;
                    float h = fsigm(po) * ftanh(cn);
                    g_h[dst][m * HH + hc] = __float2half_rn(h);
                    hs[rr][0] += h * w0v;
                    hs[rr][1] += h * w1v;
                    hs[rr][2] += h * wsv;
                }
            }
        }
        if ((tig & 1) == 0) {
#pragma unroll
            for (int rr = 0; rr < 2; rr++) {
                int rl = r0 + rr * 8;
                atomicAdd(&sred[rl * 4 + 0], hs[rr][0]);
                atomicAdd(&sred[rl * 4 + 1], hs[rr][1]);
                atomicAdd(&sred[rl * 4 + 2], hs[rr][2]);
            }
        }
    }
    __syncthreads();
    if (tid < 128) {
        int m = m0 + tid;
        float b0 = 0.0f, b1 = 0.0f;
        if (blockIdx.x == 0) { b0 = b_out[0]; b1 = b_out[1]; }
        atomicAdd(&out[(m * TT + t) * 2 + 0], sred[tid * 4 + 0] + b0);
        atomicAdd(&out[(m * TT + t) * 2 + 1], sred[tid * 4 + 1] + b1);
        atomicAdd(&out[BB * TT * 2 + m * TT + t], sred[tid * 4 + 2]);
    }
}

// ------------------------------------------------------------------ launch
extern "C" void kernel_launch(void* const* d_in, const int* in_sizes, int n_in,
                              void* d_out, int out_size) {
    const float* emb     = (const float*)d_in[0];
    const float* W_embed = (const float*)d_in[2];
    const float* b_embed = (const float*)d_in[3];
    const float* W_ih    = (const float*)d_in[4];
    const float* b_ih    = (const float*)d_in[5];
    const float* W_hh    = (const float*)d_in[6];
    const float* b_hh    = (const float*)d_in[7];
    const float* W_out   = (const float*)d_in[8];
    const float* b_out   = (const float*)d_in[9];
    const float* W_stop  = (const float*)d_in[10];
    const float* b_stop  = (const float*)d_in[11];
    float* out = (float*)d_out;

    cudaFuncSetAttribute(lstm_step_mma, cudaFuncAttributeMaxDynamicSharedMemorySize, SMEM_TOTAL);

    zero_out_kernel<<<(BB * TT * 3 + 255) / 256, 256>>>(out);
    prep_w_kernel<<<NG, 256>>>(W_hh);
    prep_misc_kernel<<<NG / 256, 256>>>(b_ih, b_hh, W_ih);
    h0_kernel<<<dim3(HH / 64, BB / 64), 256>>>(emb, W_embed, b_embed);

    for (int t = 0; t < TT; t++) {
        lstm_step_mma<<<dim3(64, 4), 256, SMEM_TOTAL>>>(out, t, W_out, W_stop, b_out);
    }
    stop_final_kernel<<<(BB * TT + 255) / 256, 256>>>(out, b_stop);
}